// round 6
// baseline (speedup 1.0000x reference)
#include <cuda_runtime.h>
#include <cstdint>

#define NBOX   8192
#define CLS    81
#define NPAD   300
#define NWORDS (NBOX / 32)      // 256 words per mask row
#define NCH    (NBOX / 64)      // 128 scan chunks of 64 boxes

// ------------------------- device scratch (static, no allocs) --------------
__device__ float4             g_selv[NBOX];     // decoded boxes (orig order)
__device__ unsigned long long g_key[NBOX];      // composite sort keys
__device__ float4             g_sbox[NBOX];     // boxes in sorted order
__device__ float              g_sarea[NBOX];    // areas in sorted order
__device__ int                g_orig[NBOX];     // sorted pos -> original idx
__device__ unsigned           g_masks[(size_t)NBOX * NWORDS]; // sorted-space IoU>0.5

// ---------------------------------------------------------------------------
// Kernel 1: per-row argmax / max + bbox decode + sort-key build. 1 warp/row.
// ---------------------------------------------------------------------------
__global__ void decode_kernel(const float* __restrict__ meta,
                              const float* __restrict__ deltas,
                              const float* __restrict__ proposals,
                              const float* __restrict__ scores) {
    int row  = (int)((blockIdx.x * blockDim.x + threadIdx.x) >> 5);
    int lane = threadIdx.x & 31;
    if (row >= NBOX) return;

    const float* srow = scores + (size_t)row * CLS;
    float best = -1.0f;
    int   bidx = 0x7FFFFFFF;
    float ms   = -1.0f;
    for (int j = lane; j < CLS; j += 32) {
        float v = srow[j];
        if (v > best) { best = v; bidx = j; }
        if (j >= 1) ms = fmaxf(ms, v);
    }
    #pragma unroll
    for (int off = 16; off; off >>= 1) {
        float ov = __shfl_down_sync(0xffffffffu, best, off);
        int   oi = __shfl_down_sync(0xffffffffu, bidx, off);
        float om = __shfl_down_sync(0xffffffffu, ms,   off);
        if (ov > best || (ov == best && oi < bidx)) { best = ov; bidx = oi; }
        ms = fmaxf(ms, om);
    }

    if (lane == 0) {
        float scale = meta[2];
        const float* p = proposals + (size_t)row * 4;
        float x1 = p[0] / scale, y1 = p[1] / scale;
        float x2 = p[2] / scale, y2 = p[3] / scale;
        float w  = x2 - x1 + 1.0f, h = y2 - y1 + 1.0f;
        float cx = x1 + 0.5f * w,  cy = y1 + 0.5f * h;

        const float* d = deltas + (size_t)row * (4 * CLS) + 4 * bidx;
        float pcx = d[0] * w + cx;
        float pcy = d[1] * h + cy;
        float pw  = expf(d[2]) * w;
        float ph  = expf(d[3]) * h;

        float W1 = meta[1] - 1.0f;
        float H1 = meta[0] - 1.0f;
        float ox1 = fminf(fmaxf(pcx - 0.5f * pw, 0.0f), W1);
        float oy1 = fminf(fmaxf(pcy - 0.5f * ph, 0.0f), H1);
        float ox2 = fminf(fmaxf(pcx + 0.5f * pw, 0.0f), W1);
        float oy2 = fminf(fmaxf(pcy + 0.5f * ph, 0.0f), H1);

        g_selv[row] = make_float4(ox1, oy1, ox2, oy2);
        unsigned int sb = __float_as_uint(ms);   // scores >= 0 -> monotonic bits
        g_key[row] = ((unsigned long long)sb << 13) |
                     (unsigned long long)(8191 - row);   // all keys distinct
    }
}

// ---------------------------------------------------------------------------
// Kernel 2: rank-by-counting + scatter into sorted order. 256 blocks.
// ---------------------------------------------------------------------------
__global__ void __launch_bounds__(256)
rank_kernel() {
    extern __shared__ unsigned long long keys[];   // 64 KB
    const int tid = threadIdx.x;
    for (int i = tid; i < NBOX; i += 256) keys[i] = g_key[i];
    __syncthreads();

    const int warp = tid >> 5, lane = tid & 31;
    const int row0 = blockIdx.x * 32 + warp * 4;

    unsigned long long rk0 = keys[row0 + 0];
    unsigned long long rk1 = keys[row0 + 1];
    unsigned long long rk2 = keys[row0 + 2];
    unsigned long long rk3 = keys[row0 + 3];
    int c0 = 0, c1 = 0, c2 = 0, c3 = 0;

    #pragma unroll 4
    for (int c = lane; c < NBOX; c += 32) {
        unsigned long long kc = keys[c];
        c0 += (kc > rk0);
        c1 += (kc > rk1);
        c2 += (kc > rk2);
        c3 += (kc > rk3);
    }
    #pragma unroll
    for (int off = 16; off; off >>= 1) {
        c0 += __shfl_down_sync(0xffffffffu, c0, off);
        c1 += __shfl_down_sync(0xffffffffu, c1, off);
        c2 += __shfl_down_sync(0xffffffffu, c2, off);
        c3 += __shfl_down_sync(0xffffffffu, c3, off);
    }
    if (lane == 0) {
        int rr[4] = {c0, c1, c2, c3};
        #pragma unroll
        for (int q = 0; q < 4; q++) {
            int i = row0 + q, r = rr[q];
            float4 b = g_selv[i];
            g_sbox[r]  = b;
            g_sarea[r] = fmaxf(b.z - b.x, 0.0f) * fmaxf(b.w - b.y, 0.0f);
            g_orig[r]  = i;
        }
    }
}

// ---------------------------------------------------------------------------
// Kernel 3: sorted-space IoU>0.5 bitmask, upper triangle only.
// ---------------------------------------------------------------------------
__global__ void __launch_bounds__(256)
mask_kernel() {
    __shared__ float4 rbs[32];
    __shared__ float  ras[32];
    __shared__ float4 cbT[32 * 33];
    __shared__ float  caT[32 * 33];

    const int m  = blockIdx.x;
    const int rb = m & 255;
    const int cb = m >> 8;
    if (cb < (rb >> 5)) return;

    const int rowbase = rb * 32;
    const int colbase = cb * 1024;
    const int tid = threadIdx.x;

    if (tid < 32) {
        rbs[tid] = g_sbox[rowbase + tid];
        ras[tid] = g_sarea[rowbase + tid];
    }
    for (int jj = tid; jj < 1024; jj += 256) {
        int w = jj >> 5, bb = jj & 31;
        cbT[bb * 33 + w] = g_sbox[colbase + jj];
        caT[bb * 33 + w] = g_sarea[colbase + jj];
    }
    __syncthreads();

    const int r0 = tid >> 5;
    const int w  = tid & 31;
    float4 bi[4];
    float  si[4];
    #pragma unroll
    for (int k = 0; k < 4; k++) {
        bi[k] = rbs[r0 + 8 * k];
        si[k] = ras[r0 + 8 * k] + 1e-8f;
    }
    unsigned bits0 = 0, bits1 = 0, bits2 = 0, bits3 = 0;

    #pragma unroll
    for (int b = 0; b < 32; b++) {
        float4 bj = cbT[b * 33 + w];
        float  aj = caT[b * 33 + w];
        #pragma unroll
        for (int k = 0; k < 4; k++) {
            float xx1 = fmaxf(bi[k].x, bj.x), yy1 = fmaxf(bi[k].y, bj.y);
            float xx2 = fminf(bi[k].z, bj.z), yy2 = fminf(bi[k].w, bj.w);
            float iw  = fmaxf(xx2 - xx1, 0.0f);
            float ih  = fmaxf(yy2 - yy1, 0.0f);
            float inter = iw * ih;
            unsigned p = (3.0f * inter > si[k] + aj) ? (1u << b) : 0u;
            if (k == 0) bits0 |= p;
            else if (k == 1) bits1 |= p;
            else if (k == 2) bits2 |= p;
            else bits3 |= p;
        }
    }
    size_t base = (size_t)rowbase * NWORDS + (size_t)cb * 32 + w;
    g_masks[base + (size_t)(r0 +  0) * NWORDS] = bits0;
    g_masks[base + (size_t)(r0 +  8) * NWORDS] = bits1;
    g_masks[base + (size_t)(r0 + 16) * NWORDS] = bits2;
    g_masks[base + (size_t)(r0 + 24) * NWORDS] = bits3;
}

// ---------------------------------------------------------------------------
// Kernel 4: two-stage pipelined greedy scan, 64-box chunks (1 block x 256).
//  warp 0  : resolution only (prefetched conf/next regs, supfix fast path)
//  tid>=32 : row-OR suppression, issued at chunk c for keeps of c-1,
//            applied at chunk c+1  -> load latency fully off the chain.
//  sup_s lags 2 chunks; supfix (registers) covers the missing chunk.
// ---------------------------------------------------------------------------
__global__ void __launch_bounds__(256)
scan_kernel(const float* __restrict__ scores, float* __restrict__ out) {
    __shared__ unsigned           sup_s[NWORDS];
    __shared__ unsigned long long kbuf64[2];
    __shared__ int                kcnt[2];
    __shared__ int                s_keep[NPAD];

    const int tid  = threadIdx.x;
    const int lane = tid & 31;
    sup_s[tid] = 0u;
    if (tid == 0) { kbuf64[0] = kbuf64[1] = 0ull; kcnt[0] = kcnt[1] = 0; }
    __syncthreads();

    // warp 0: prefetch chunk 0 conf (words 0,1) + next (words 2,3)
    unsigned long long confA = 0, confB = 0, nxtA = 0, nxtB = 0, supfix = 0;
    if (tid < 32) {
        const unsigned* rA = &g_masks[(size_t)lane        * NWORDS];
        const unsigned* rB = &g_masks[(size_t)(lane + 32) * NWORDS];
        confA = (unsigned long long)__ldg(rA + 0) | ((unsigned long long)__ldg(rA + 1) << 32);
        confB = (unsigned long long)__ldg(rB + 0) | ((unsigned long long)__ldg(rB + 1) << 32);
        nxtA  = (unsigned long long)__ldg(rA + 2) | ((unsigned long long)__ldg(rA + 3) << 32);
        nxtB  = (unsigned long long)__ldg(rB + 2) | ((unsigned long long)__ldg(rB + 3) << 32);
    }

    // background word assignment: 224 threads cover 256 words
    const int w0 = tid - 32;                       // valid when tid >= 32
    const int w1 = (w0 >= 0 && w0 < 32) ? (w0 + 224) : -1;
    unsigned bacc0 = 0u, bacc1 = 0u;

    for (int c = 0; c < NCH; c++) {
        // stage A: apply suppression loaded last iteration (keeps of c-2)
        if (tid >= 32) {
            if (bacc0) sup_s[w0] |= bacc0;
            if (w1 >= 0 && bacc1) sup_s[w1] |= bacc1;
        }
        __syncthreads();   // sup_s(<=c-2), kbuf64[c-1], kcnt[c-1] visible
        if (c > 0 && kcnt[(c - 1) & 1] >= NPAD) break;   // uniform

        if (tid < 32) {
            // availability: lagged sup words + register fast-correction
            unsigned long long sup64 =
                (unsigned long long)sup_s[2 * c] |
                ((unsigned long long)sup_s[2 * c + 1] << 32);
            unsigned long long am = ~(sup64 | supfix);
            unsigned long long keepm = 0ull;
            while (am) {
                int l = __ffsll((long long)am) - 1;
                keepm |= 1ull << l;
                unsigned long long cl = (l < 32)
                    ? __shfl_sync(0xffffffffu, confA, l)
                    : __shfl_sync(0xffffffffu, confB, l - 32);
                am &= ~cl;
                am &= ~(1ull << l);
            }

            // fast path: this chunk's keeps -> next chunk's two words
            unsigned long long v = 0ull;
            if ((keepm >> lane) & 1ull)        v |= nxtA;
            if ((keepm >> (lane + 32)) & 1ull) v |= nxtB;
            #pragma unroll
            for (int off = 16; off; off >>= 1)
                v |= __shfl_xor_sync(0xffffffffu, v, off);
            supfix = v;

            // prefetch chunk c+1 (static addresses; consumed next iteration)
            if (c + 1 < NCH) {
                const unsigned* rA =
                    &g_masks[(size_t)(64 * (c + 1) + lane) * NWORDS];
                const unsigned* rB = rA + (size_t)32 * NWORDS;
                int wc  = 2 * (c + 1);
                int wn0 = (wc + 2 < NWORDS) ? wc + 2 : NWORDS - 1;
                int wn1 = (wc + 3 < NWORDS) ? wc + 3 : NWORDS - 1;
                confA = (unsigned long long)__ldg(rA + wc)  | ((unsigned long long)__ldg(rA + wc + 1) << 32);
                confB = (unsigned long long)__ldg(rB + wc)  | ((unsigned long long)__ldg(rB + wc + 1) << 32);
                nxtA  = (unsigned long long)__ldg(rA + wn0) | ((unsigned long long)__ldg(rA + wn1) << 32);
                nxtB  = (unsigned long long)__ldg(rB + wn0) | ((unsigned long long)__ldg(rB + wn1) << 32);
            }

            if (lane == 0) {
                kbuf64[c & 1] = keepm;
                int k2 = kcnt[(c + 1) & 1];        // cumulative through c-1
                unsigned long long km = keepm;
                while (km && k2 < NPAD) {
                    int l = __ffsll((long long)km) - 1; km &= km - 1;
                    s_keep[k2++] = c * 64 + l;
                }
                kcnt[c & 1] = k2;
            }
        } else {
            // stage B: issue row-OR loads for keeps of chunk c-1
            bacc0 = 0u; bacc1 = 0u;
            if (c > 0) {
                unsigned long long km = kbuf64[(c - 1) & 1];
                const size_t prevbase = (size_t)(c - 1) * 64;
                while (km) {
                    int l = __ffsll((long long)km) - 1; km &= km - 1;
                    const unsigned* row = &g_masks[(prevbase + l) * NWORDS];
                    bacc0 |= __ldg(row + w0);
                    if (w1 >= 0) bacc1 |= __ldg(row + w1);
                }
            }
        }
    }
    __syncthreads();
    const int nk = (kcnt[0] > kcnt[1]) ? kcnt[0] : kcnt[1];   // cumulative, capped

    // ---- outputs: boxes (300*4) then scores (300*81); zero invalid rows ----
    for (int idx = tid; idx < NPAD * 4; idx += 256) {
        int r = idx >> 2, cc = idx & 3;
        float v = 0.0f;
        if (r < nk) {
            float4 b = g_sbox[s_keep[r]];
            v = (cc == 0) ? b.x : (cc == 1) ? b.y : (cc == 2) ? b.z : b.w;
        }
        out[idx] = v;
    }
    for (int idx = tid; idx < NPAD * CLS; idx += 256) {
        int r = idx / CLS, cc = idx - r * CLS;
        float v = 0.0f;
        if (r < nk)
            v = scores[(size_t)g_orig[s_keep[r]] * CLS + cc];
        out[NPAD * 4 + idx] = v;
    }
}

// ---------------------------------------------------------------------------
extern "C" void kernel_launch(void* const* d_in, const int* in_sizes, int n_in,
                              void* d_out, int out_size) {
    const float* meta      = (const float*)d_in[0];
    const float* deltas    = (const float*)d_in[1];
    const float* proposals = (const float*)d_in[2];
    const float* scores    = (const float*)d_in[3];
    float* out = (float*)d_out;

    decode_kernel<<<NBOX / 8, 256>>>(meta, deltas, proposals, scores);

    cudaFuncSetAttribute(rank_kernel,
                         cudaFuncAttributeMaxDynamicSharedMemorySize, 65536);
    rank_kernel<<<256, 256, 65536>>>();

    mask_kernel<<<2048, 256>>>();

    scan_kernel<<<1, 256>>>(scores, out);
}

// round 7
// speedup vs baseline: 1.0333x; 1.0333x over previous
#include <cuda_runtime.h>
#include <cstdint>

#define NBOX   8192
#define CLS    81
#define NPAD   300
#define NWORDS (NBOX / 32)      // 256 words per mask row
#define NCH    (NBOX / 64)      // 128 scan chunks of 64 boxes

// ------------------------- device scratch (static, no allocs) --------------
__device__ float4             g_selv[NBOX];     // decoded boxes (orig order)
__device__ unsigned long long g_key[NBOX];      // composite sort keys
__device__ float4             g_sbox[NBOX];     // boxes in sorted order
__device__ float              g_sarea[NBOX];    // areas in sorted order
__device__ int                g_orig[NBOX];     // sorted pos -> original idx
__device__ unsigned           g_masks[(size_t)NBOX * NWORDS]; // sorted-space IoU>0.5

// ---------------------------------------------------------------------------
// Kernel 1: per-row argmax / max + bbox decode + sort-key build. 1 warp/row.
// ---------------------------------------------------------------------------
__global__ void decode_kernel(const float* __restrict__ meta,
                              const float* __restrict__ deltas,
                              const float* __restrict__ proposals,
                              const float* __restrict__ scores) {
    int row  = (int)((blockIdx.x * blockDim.x + threadIdx.x) >> 5);
    int lane = threadIdx.x & 31;
    if (row >= NBOX) return;

    const float* srow = scores + (size_t)row * CLS;
    float best = -1.0f;
    int   bidx = 0x7FFFFFFF;
    float ms   = -1.0f;
    for (int j = lane; j < CLS; j += 32) {
        float v = srow[j];
        if (v > best) { best = v; bidx = j; }
        if (j >= 1) ms = fmaxf(ms, v);
    }
    #pragma unroll
    for (int off = 16; off; off >>= 1) {
        float ov = __shfl_down_sync(0xffffffffu, best, off);
        int   oi = __shfl_down_sync(0xffffffffu, bidx, off);
        float om = __shfl_down_sync(0xffffffffu, ms,   off);
        if (ov > best || (ov == best && oi < bidx)) { best = ov; bidx = oi; }
        ms = fmaxf(ms, om);
    }

    if (lane == 0) {
        float scale = meta[2];
        const float* p = proposals + (size_t)row * 4;
        float x1 = p[0] / scale, y1 = p[1] / scale;
        float x2 = p[2] / scale, y2 = p[3] / scale;
        float w  = x2 - x1 + 1.0f, h = y2 - y1 + 1.0f;
        float cx = x1 + 0.5f * w,  cy = y1 + 0.5f * h;

        const float* d = deltas + (size_t)row * (4 * CLS) + 4 * bidx;
        float pcx = d[0] * w + cx;
        float pcy = d[1] * h + cy;
        float pw  = expf(d[2]) * w;
        float ph  = expf(d[3]) * h;

        float W1 = meta[1] - 1.0f;
        float H1 = meta[0] - 1.0f;
        float ox1 = fminf(fmaxf(pcx - 0.5f * pw, 0.0f), W1);
        float oy1 = fminf(fmaxf(pcy - 0.5f * ph, 0.0f), H1);
        float ox2 = fminf(fmaxf(pcx + 0.5f * pw, 0.0f), W1);
        float oy2 = fminf(fmaxf(pcy + 0.5f * ph, 0.0f), H1);

        g_selv[row] = make_float4(ox1, oy1, ox2, oy2);
        unsigned int sb = __float_as_uint(ms);   // scores >= 0 -> monotonic bits
        g_key[row] = ((unsigned long long)sb << 13) |
                     (unsigned long long)(8191 - row);   // all keys distinct
    }
}

// ---------------------------------------------------------------------------
// Kernel 2: rank-by-counting + scatter into sorted order. 256 blocks.
// ---------------------------------------------------------------------------
__global__ void __launch_bounds__(256)
rank_kernel() {
    extern __shared__ unsigned long long keys[];   // 64 KB
    const int tid = threadIdx.x;
    for (int i = tid; i < NBOX; i += 256) keys[i] = g_key[i];
    __syncthreads();

    const int warp = tid >> 5, lane = tid & 31;
    const int row0 = blockIdx.x * 32 + warp * 4;

    unsigned long long rk0 = keys[row0 + 0];
    unsigned long long rk1 = keys[row0 + 1];
    unsigned long long rk2 = keys[row0 + 2];
    unsigned long long rk3 = keys[row0 + 3];
    int c0 = 0, c1 = 0, c2 = 0, c3 = 0;

    #pragma unroll 4
    for (int c = lane; c < NBOX; c += 32) {
        unsigned long long kc = keys[c];
        c0 += (kc > rk0);
        c1 += (kc > rk1);
        c2 += (kc > rk2);
        c3 += (kc > rk3);
    }
    #pragma unroll
    for (int off = 16; off; off >>= 1) {
        c0 += __shfl_down_sync(0xffffffffu, c0, off);
        c1 += __shfl_down_sync(0xffffffffu, c1, off);
        c2 += __shfl_down_sync(0xffffffffu, c2, off);
        c3 += __shfl_down_sync(0xffffffffu, c3, off);
    }
    if (lane == 0) {
        int rr[4] = {c0, c1, c2, c3};
        #pragma unroll
        for (int q = 0; q < 4; q++) {
            int i = row0 + q, r = rr[q];
            float4 b = g_selv[i];
            g_sbox[r]  = b;
            g_sarea[r] = fmaxf(b.z - b.x, 0.0f) * fmaxf(b.w - b.y, 0.0f);
            g_orig[r]  = i;
        }
    }
}

// ---------------------------------------------------------------------------
// Kernel 3: sorted-space IoU>0.5 bitmask, upper triangle only.
// ---------------------------------------------------------------------------
__global__ void __launch_bounds__(256)
mask_kernel() {
    __shared__ float4 rbs[32];
    __shared__ float  ras[32];
    __shared__ float4 cbT[32 * 33];
    __shared__ float  caT[32 * 33];

    const int m  = blockIdx.x;
    const int rb = m & 255;
    const int cb = m >> 8;
    if (cb < (rb >> 5)) return;

    const int rowbase = rb * 32;
    const int colbase = cb * 1024;
    const int tid = threadIdx.x;

    if (tid < 32) {
        rbs[tid] = g_sbox[rowbase + tid];
        ras[tid] = g_sarea[rowbase + tid];
    }
    for (int jj = tid; jj < 1024; jj += 256) {
        int w = jj >> 5, bb = jj & 31;
        cbT[bb * 33 + w] = g_sbox[colbase + jj];
        caT[bb * 33 + w] = g_sarea[colbase + jj];
    }
    __syncthreads();

    const int r0 = tid >> 5;
    const int w  = tid & 31;
    float4 bi[4];
    float  si[4];
    #pragma unroll
    for (int k = 0; k < 4; k++) {
        bi[k] = rbs[r0 + 8 * k];
        si[k] = ras[r0 + 8 * k] + 1e-8f;
    }
    unsigned bits0 = 0, bits1 = 0, bits2 = 0, bits3 = 0;

    #pragma unroll
    for (int b = 0; b < 32; b++) {
        float4 bj = cbT[b * 33 + w];
        float  aj = caT[b * 33 + w];
        #pragma unroll
        for (int k = 0; k < 4; k++) {
            float xx1 = fmaxf(bi[k].x, bj.x), yy1 = fmaxf(bi[k].y, bj.y);
            float xx2 = fminf(bi[k].z, bj.z), yy2 = fminf(bi[k].w, bj.w);
            float iw  = fmaxf(xx2 - xx1, 0.0f);
            float ih  = fmaxf(yy2 - yy1, 0.0f);
            float inter = iw * ih;
            unsigned p = (3.0f * inter > si[k] + aj) ? (1u << b) : 0u;
            if (k == 0) bits0 |= p;
            else if (k == 1) bits1 |= p;
            else if (k == 2) bits2 |= p;
            else bits3 |= p;
        }
    }
    size_t base = (size_t)rowbase * NWORDS + (size_t)cb * 32 + w;
    g_masks[base + (size_t)(r0 +  0) * NWORDS] = bits0;
    g_masks[base + (size_t)(r0 +  8) * NWORDS] = bits1;
    g_masks[base + (size_t)(r0 + 16) * NWORDS] = bits2;
    g_masks[base + (size_t)(r0 + 24) * NWORDS] = bits3;
}

// ---------------------------------------------------------------------------
// Kernel 4: greedy scan, single-thread resolution over smem-staged operands.
//  thread 0        : resolve chunk c from sup_s + supfix + confb/n1b/n2b[c&1]
//  tids 32..223    : prefetch chunk c+1 operands (conf/n1/n2 -> smem, dbuf)
//  tids 32..255    : row-OR suppression for keeps(c-1), issued iter c,
//                    applied iter c+2 (register shift b1->b2)  [lag-3]
//  supfix = n1acc(keeps c-1) | n2acc(keeps c-2)  covers the lag gap.
// ---------------------------------------------------------------------------
__global__ void __launch_bounds__(256)
scan_kernel(const float* __restrict__ scores, float* __restrict__ out) {
    __shared__ unsigned           sup_s[NWORDS];
    __shared__ unsigned long long kbuf64[2];
    __shared__ int                kcnt[2];
    __shared__ int                s_keep[NPAD];
    __shared__ unsigned long long confb[2][64];   // diag words of chunk
    __shared__ unsigned long long n1b[2][64];     // words of chunk+1
    __shared__ unsigned long long n2b[2][64];     // words of chunk+2

    const int tid = threadIdx.x;
    sup_s[tid] = 0u;
    if (tid == 0) { kbuf64[0] = kbuf64[1] = 0ull; kcnt[0] = kcnt[1] = 0; }

    // prefill chunk 0 operand buffers (192 threads: 64 rows x 3 fields)
    if (tid >= 32 && tid < 224) {
        int e = tid - 32, row = e / 3, f = e - row * 3;
        const unsigned* r = &g_masks[(size_t)row * NWORDS];
        int w = 2 * f;                      // conf=0, n1=2, n2=4
        unsigned long long v = (unsigned long long)__ldg(r + w) |
                               ((unsigned long long)__ldg(r + w + 1) << 32);
        if (f == 0) confb[0][row] = v;
        else if (f == 1) n1b[0][row] = v;
        else n2b[0][row] = v;
    }
    __syncthreads();

    unsigned long long supfix = 0ull, carry = 0ull;   // thread 0 only
    unsigned b1a = 0u, b1b = 0u, b2a = 0u, b2b = 0u;  // bacc shift pipeline
    const int w0 = tid - 32;
    const int w1 = (w0 >= 0 && w0 < 32) ? w0 + 224 : -1;
    int nk_local = 0;                                  // thread 0 only

    for (int c = 0; c < NCH; c++) {
        // ---- stage A: apply suppression issued 2 iters ago (keeps c-3) ----
        if (tid >= 32) {
            if (b2a) sup_s[w0] |= b2a;
            if (w1 >= 0 && b2b) sup_s[w1] |= b2b;
        }
        __syncthreads();   // sup_s(<=c-3), kbuf/kcnt(c-1), operands(c) visible
        if (c > 0 && kcnt[(c - 1) & 1] >= NPAD) break;   // uniform

        if (tid == 0) {
            // ---- resolution: pure smem/register chain ----
            const int b = c & 1;
            unsigned long long sup64 =
                (unsigned long long)sup_s[2 * c] |
                ((unsigned long long)sup_s[2 * c + 1] << 32);
            unsigned long long am = ~(sup64 | supfix);
            unsigned long long keepm = 0ull, n1acc = 0ull, n2acc = 0ull;
            int k2 = nk_local;
            while (am) {
                int l = __ffsll((long long)am) - 1;
                keepm |= 1ull << l;
                unsigned long long cl = confb[b][l];
                n1acc |= n1b[b][l];
                n2acc |= n2b[b][l];
                am &= ~cl;
                am &= ~(1ull << l);
                if (k2 < NPAD) s_keep[k2++] = c * 64 + l;
            }
            kbuf64[b] = keepm;
            kcnt[b]   = k2;
            nk_local  = k2;
            supfix = carry | n1acc;   // covers keeps(c) @ chunk c+1
            carry  = n2acc;           // covers keeps(c) @ chunk c+2
        } else {
            // ---- prefetch chunk c+1 operands into smem (dbuf) ----
            const int cn = c + 1;
            if (cn < NCH && tid < 224) {
                int e = tid - 32, row = e / 3, f = e - row * 3;
                const unsigned* r = &g_masks[(size_t)(64 * cn + row) * NWORDS];
                int w = 2 * cn + 2 * f;
                if (w > NWORDS - 2) w = NWORDS - 2;   // clamp; tail unused
                unsigned long long v = (unsigned long long)__ldg(r + w) |
                                       ((unsigned long long)__ldg(r + w + 1) << 32);
                if (f == 0) confb[cn & 1][row] = v;
                else if (f == 1) n1b[cn & 1][row] = v;
                else n2b[cn & 1][row] = v;
            }
            // ---- stage B: issue row-OR loads for keeps(c-1); lands c+2 ----
            unsigned a0 = 0u, a1 = 0u;
            if (c > 0) {
                unsigned long long km = kbuf64[(c - 1) & 1];
                const size_t pb = (size_t)(c - 1) * 64;
                while (km) {
                    int l = __ffsll((long long)km) - 1; km &= km - 1;
                    const unsigned* row = &g_masks[(pb + l) * NWORDS];
                    a0 |= __ldg(row + w0);
                    if (w1 >= 0) a1 |= __ldg(row + w1);
                }
            }
            b2a = b1a; b2b = b1b;     // shift: previous issue -> apply next
            b1a = a0;  b1b = a1;
        }
    }
    __syncthreads();
    const int nk = (kcnt[0] > kcnt[1]) ? kcnt[0] : kcnt[1];   // cumulative

    // ---- outputs: boxes (300*4) then scores (300*81); zero invalid rows ----
    for (int idx = tid; idx < NPAD * 4; idx += 256) {
        int r = idx >> 2, cc = idx & 3;
        float v = 0.0f;
        if (r < nk) {
            float4 b = g_sbox[s_keep[r]];
            v = (cc == 0) ? b.x : (cc == 1) ? b.y : (cc == 2) ? b.z : b.w;
        }
        out[idx] = v;
    }
    for (int idx = tid; idx < NPAD * CLS; idx += 256) {
        int r = idx / CLS, cc = idx - r * CLS;
        float v = 0.0f;
        if (r < nk)
            v = scores[(size_t)g_orig[s_keep[r]] * CLS + cc];
        out[NPAD * 4 + idx] = v;
    }
}

// ---------------------------------------------------------------------------
extern "C" void kernel_launch(void* const* d_in, const int* in_sizes, int n_in,
                              void* d_out, int out_size) {
    const float* meta      = (const float*)d_in[0];
    const float* deltas    = (const float*)d_in[1];
    const float* proposals = (const float*)d_in[2];
    const float* scores    = (const float*)d_in[3];
    float* out = (float*)d_out;

    decode_kernel<<<NBOX / 8, 256>>>(meta, deltas, proposals, scores);

    cudaFuncSetAttribute(rank_kernel,
                         cudaFuncAttributeMaxDynamicSharedMemorySize, 65536);
    rank_kernel<<<256, 256, 65536>>>();

    mask_kernel<<<2048, 256>>>();

    scan_kernel<<<1, 256>>>(scores, out);
}